// round 14
// baseline (speedup 1.0000x reference)
#include <cuda_runtime.h>
#include <cuda_fp16.h>
#include <mma.h>
#include <cstdint>
using namespace nvcuda;

// Problem constants
#define NMAX   50000
#define EMAX   800000
#define TOTMAX (EMAX + NMAX)
#define GRAPHS 256
#define HC     256      // H*C
#define KIN    300      // n_in
#define KPAD   320      // padded K for fp16 GEMM
#define FOUT   768      // nout

// ---------------- scratch (device globals; no allocation) ----------------
__device__ __half g_xh[NMAX * KPAD];  // fp16 X, K padded with zeros
__device__ __half g_wh[KPAD * HC];    // fp16 W, K padded with zeros
__device__ __half g_hh[NMAX * HC];    // node features after linear, fp16 [N,256]
__device__ float  g_asrc[NMAX * 4];   // per-node src attention logits [N,4] (fp32)
__device__ float  g_adst[NMAX * 4];   // per-node dst attention logits [N,4] (fp32)
__device__ int    g_count[NMAX];      // in-degree (incl self-loop)
__device__ int    g_scanex[NMAX];     // per-chunk exclusive scan
__device__ int    g_bsum[64];         // chunk totals -> chunk offsets
__device__ int    g_rowoff[NMAX];     // CSR row offsets
__device__ int    g_cursor[NMAX];     // fill cursors
__device__ int    g_csrc[TOTMAX];     // CSR-ordered src ids
__device__ float  g_pool[GRAPHS * HC];// per-graph sums [G,256]
__device__ float  g_cnt[GRAPHS];      // per-graph node counts

// ---------------- 0: init scratch ----------------
__global__ void init_kernel(int M) {
    int i = blockIdx.x * blockDim.x + threadIdx.x;
    if (i < M)            g_count[i] = 1;   // self-loop pre-counted
    if (i < GRAPHS * HC)  g_pool[i]  = 0.0f;
    if (i < GRAPHS)       g_cnt[i]   = 0.0f;
}

// ---------------- 1: convert X, W to fp16 (K padded to 320) ----------------
__global__ void convert_kernel(const float* __restrict__ X,
                               const float* __restrict__ W, int M) {
    int i = blockIdx.x * blockDim.x + threadIdx.x;
    if (i < M * (KPAD / 4)) {
        int row = i / (KPAD / 4);
        int c4  = (i % (KPAD / 4)) * 4;
        float4 v = make_float4(0.f, 0.f, 0.f, 0.f);
        if (c4 < KIN) v = *(const float4*)&X[row * KIN + c4];   // KIN divisible by 4
        *(__half2*)&g_xh[row * KPAD + c4]     = __float22half2_rn(make_float2(v.x, v.y));
        *(__half2*)&g_xh[row * KPAD + c4 + 2] = __float22half2_rn(make_float2(v.z, v.w));
    }
    if (i < KPAD * (HC / 4)) {
        int row = i / (HC / 4);
        int c4  = (i % (HC / 4)) * 4;
        float4 v = make_float4(0.f, 0.f, 0.f, 0.f);
        if (row < KIN) v = *(const float4*)&W[row * HC + c4];
        *(__half2*)&g_wh[row * HC + c4]     = __float22half2_rn(make_float2(v.x, v.y));
        *(__half2*)&g_wh[row * HC + c4 + 2] = __float22half2_rn(make_float2(v.z, v.w));
    }
}

// ---------------- 2: degree count (dst only; self-loops pre-counted) ----------------
__global__ void edge_count_kernel(const int* __restrict__ ei, int E) {
    int i = blockIdx.x * blockDim.x + threadIdx.x;
    if (i >= E) return;
    atomicAdd(&g_count[ei[E + i]], 1);
}

// ---------------- 3: h = xh @ wh via fp16 wmma + cp.async double buffering ----------
// Block 128x128, BKW=64 (4 k16 steps), 8 warps (4x2), warp tile 32x64.
#define BM 128
#define BKW 64
#define KP 72     // A smem stride (half), 144B rows — ldmatrix conflict-free
#define NP 136    // B smem stride (half), 272B rows — ldmatrix conflict-free
#define NCHUNK (KPAD / BKW)   // 5
// dynamic smem layout (bytes): A0 | A1 | B0 | B1
#define SMA0 0
#define SMA1 18432
#define SMB0 36864
#define SMB1 54272
#define SMTOT 71680           // epilogue staging reuses offset 0 (8*16*68*4 = 34816)

__device__ __forceinline__ void cp_async16(uint32_t saddr, const void* g, int srcsz) {
    asm volatile("cp.async.cg.shared.global [%0], [%1], 16, %2;"
                 :: "r"(saddr), "l"(g), "r"(srcsz));
}

__global__ __launch_bounds__(256)
void gemm_h_kernel(const float* __restrict__ att_s,
                   const float* __restrict__ att_d,
                   int M) {
    extern __shared__ __align__(16) unsigned char dsm[];
    __shared__ float s_as[128], s_ad[128];

    const int bx   = blockIdx.x;          // 0..1 -> N offset bx*128
    const int row0 = blockIdx.y * BM;
    const int tid  = threadIdx.x;
    const int warp = tid >> 5;
    const int lane = tid & 31;
    const int wm   = warp >> 1;           // 0..3 (M: wm*32)
    const int wn   = warp & 1;            // 0..1 (N: wn*64)
    const uint32_t sbase = (uint32_t)__cvta_generic_to_shared(dsm);

    if (tid < 128) { s_as[tid] = att_s[bx * 128 + tid]; s_ad[tid] = att_d[bx * 128 + tid]; }

    wmma::fragment<wmma::accumulator, 16, 16, 16, float> acc[2][4];
#pragma unroll
    for (int mt = 0; mt < 2; mt++)
#pragma unroll
        for (int nt = 0; nt < 4; nt++) wmma::fill_fragment(acc[mt][nt], 0.0f);

    // prefetch chunk c into buffer (c&1)
    auto prefetch = [&](int c) {
        const int k0 = c * BKW;
        uint32_t abuf = sbase + ((c & 1) ? SMA1 : SMA0);
        uint32_t bbuf = sbase + ((c & 1) ? SMB1 : SMB0);
#pragma unroll
        for (int it = 0; it < 4; it++) {
            int q   = tid + it * 256;
            int row = q >> 3;
            int c8  = (q & 7) * 8;
            int gr  = row0 + row;
            int grc = gr < M ? gr : 0;
            cp_async16(abuf + (uint32_t)(row * KP + c8) * 2,
                       &g_xh[(long long)grc * KPAD + k0 + c8], gr < M ? 16 : 0);
        }
#pragma unroll
        for (int it = 0; it < 4; it++) {
            int q  = tid + it * 256;
            int kk = q >> 4;
            int c8 = (q & 15) * 8;
            cp_async16(bbuf + (uint32_t)(kk * NP + c8) * 2,
                       &g_wh[(k0 + kk) * HC + bx * 128 + c8], 16);
        }
        asm volatile("cp.async.commit_group;" ::: "memory");
    };

    prefetch(0);

    for (int c = 0; c < NCHUNK; c++) {
        asm volatile("cp.async.wait_group 0;" ::: "memory");
        __syncthreads();
        if (c + 1 < NCHUNK) prefetch(c + 1);

        __half* Ah = (__half*)(dsm + ((c & 1) ? SMA1 : SMA0));
        __half* Bh = (__half*)(dsm + ((c & 1) ? SMB1 : SMB0));
#pragma unroll
        for (int ks = 0; ks < 4; ks++) {
            int kk16 = ks * 16;
            wmma::fragment<wmma::matrix_a, 16, 16, 16, __half, wmma::row_major> af[2];
            wmma::fragment<wmma::matrix_b, 16, 16, 16, __half, wmma::row_major> bf[4];
#pragma unroll
            for (int mt = 0; mt < 2; mt++)
                wmma::load_matrix_sync(af[mt], &Ah[(wm * 32 + mt * 16) * KP + kk16], KP);
#pragma unroll
            for (int nt = 0; nt < 4; nt++)
                wmma::load_matrix_sync(bf[nt], &Bh[kk16 * NP + wn * 64 + nt * 16], NP);
#pragma unroll
            for (int mt = 0; mt < 2; mt++)
#pragma unroll
                for (int nt = 0; nt < 4; nt++)
                    wmma::mma_sync(acc[mt][nt], af[mt], bf[nt], acc[mt][nt]);
        }
    }
    __syncthreads();   // before staging reuses dsm

    // epilogue: per-warp staging, fp16 h store + fused fp32 att dots
    float* eb = (float*)dsm + warp * 16 * 68;
#pragma unroll
    for (int mt = 0; mt < 2; mt++) {
#pragma unroll
        for (int nt = 0; nt < 4; nt++)
            wmma::store_matrix_sync(&eb[nt * 16], acc[mt][nt], 68, wmma::mem_row_major);
        __syncwarp();
        int r   = lane >> 1;
        int chh = (lane & 1) * 32;
        int gr  = row0 + wm * 32 + mt * 16 + r;
        float s = 0.f, d = 0.f;
#pragma unroll
        for (int j = 0; j < 8; j++) {
            float4 v = *(float4*)&eb[r * 68 + chh + j * 4];
            int cb = wn * 64 + chh + j * 4;
            s += v.x * s_as[cb] + v.y * s_as[cb + 1] + v.z * s_as[cb + 2] + v.w * s_as[cb + 3];
            d += v.x * s_ad[cb] + v.y * s_ad[cb + 1] + v.z * s_ad[cb + 2] + v.w * s_ad[cb + 3];
            if (gr < M) {
                *(__half2*)&g_hh[(long long)gr * HC + bx * 128 + cb]     =
                    __float22half2_rn(make_float2(v.x, v.y));
                *(__half2*)&g_hh[(long long)gr * HC + bx * 128 + cb + 2] =
                    __float22half2_rn(make_float2(v.z, v.w));
            }
        }
        s += __shfl_xor_sync(0xffffffffu, s, 1);
        d += __shfl_xor_sync(0xffffffffu, d, 1);
        if ((lane & 1) == 0 && gr < M) {
            g_asrc[gr * 4 + bx * 2 + wn] = s;
            g_adst[gr * 4 + bx * 2 + wn] = d;
        }
        __syncwarp();
    }
}

// ---------------- 4: scan ----------------
__global__ void scan1_kernel(int M) {                     // block=1024
    __shared__ int sh[2][1024];
    int i = blockIdx.x * 1024 + threadIdx.x;
    int v = (i < M) ? g_count[i] : 0;
    int buf = 0;
    sh[0][threadIdx.x] = v;
    __syncthreads();
#pragma unroll
    for (int off = 1; off < 1024; off <<= 1) {
        int nv = sh[buf][threadIdx.x];
        if (threadIdx.x >= off) nv += sh[buf][threadIdx.x - off];
        sh[1 - buf][threadIdx.x] = nv;
        buf = 1 - buf;
        __syncthreads();
    }
    int incl = sh[buf][threadIdx.x];
    if (i < M) g_scanex[i] = incl - v;
    if (threadIdx.x == 1023) g_bsum[blockIdx.x] = incl;
}

__global__ void scan2_kernel(int nb) {                    // 1 block of 64 threads
    __shared__ int sh[2][64];
    int t = threadIdx.x;
    int v = (t < nb) ? g_bsum[t] : 0;
    int buf = 0;
    sh[0][t] = v;
    __syncthreads();
#pragma unroll
    for (int off = 1; off < 64; off <<= 1) {
        int nv = sh[buf][t];
        if (t >= off) nv += sh[buf][t - off];
        sh[1 - buf][t] = nv;
        buf = 1 - buf;
        __syncthreads();
    }
    if (t < nb) g_bsum[t] = sh[buf][t] - v;   // exclusive
}

__global__ void scan3_kernel(int M) {
    int i = blockIdx.x * blockDim.x + threadIdx.x;
    if (i >= M) return;
    int off = g_scanex[i] + g_bsum[i >> 10];
    g_rowoff[i] = off;
    g_cursor[i] = off;
}

// ---------------- 5: CSR fill (src ids only) ----------------
__global__ void edge_fill_kernel(const int* __restrict__ ei, int E, int M) {
    int i = blockIdx.x * blockDim.x + threadIdx.x;
    int total = E + M;
    if (i >= total) return;
    int s, d;
    if (i < E) { s = ei[i]; d = ei[E + i]; }
    else       { s = d = i - E; }
    int pos = atomicAdd(&g_cursor[d], 1);
    g_csrc[pos] = s;
}

// ---------------- 6: gather-aggregate (warp/node, unroll-2) + pool ----------------
__device__ __forceinline__ float head_sel(float4 v, int hsel) {
    return (hsel == 0) ? v.x : (hsel == 1) ? v.y : (hsel == 2) ? v.z : v.w;
}

__global__ void aggregate_kernel(const int* __restrict__ batch,
                                 const float* __restrict__ bias, int M) {
    int w = blockIdx.x * (blockDim.x >> 5) + (threadIdx.x >> 5);
    if (w >= M) return;
    int lane = threadIdx.x & 31;
    int start = g_rowoff[w];
    int end   = start + g_count[w];
    int hsel  = lane >> 3;                      // head for this thread's 8 channels

    float adh = head_sel(((const float4*)g_adst)[w], hsel);

    float acc[8];
#pragma unroll
    for (int k = 0; k < 8; k++) acc[k] = 0.0f;
    float wsum = 0.0f;

    int j = start;
    for (; j + 2 <= end; j += 2) {
        int s0 = g_csrc[j];
        int s1 = g_csrc[j + 1];
        float4 as0 = ((const float4*)g_asrc)[s0];
        float4 as1 = ((const float4*)g_asrc)[s1];
        uint4 hv0 = *(const uint4*)&g_hh[(long long)s0 * HC + lane * 8];
        uint4 hv1 = *(const uint4*)&g_hh[(long long)s1 * HC + lane * 8];
        float e0 = head_sel(as0, hsel) + adh;
        float e1 = head_sel(as1, hsel) + adh;
        e0 = e0 > 0.f ? e0 : 0.2f * e0;
        e1 = e1 > 0.f ? e1 : 0.2f * e1;
        float ee0 = __expf(e0), ee1 = __expf(e1);
        wsum += ee0 + ee1;
        float2 a0 = __half22float2(*(const __half2*)&hv0.x);
        float2 a1 = __half22float2(*(const __half2*)&hv0.y);
        float2 a2 = __half22float2(*(const __half2*)&hv0.z);
        float2 a3 = __half22float2(*(const __half2*)&hv0.w);
        float2 b0 = __half22float2(*(const __half2*)&hv1.x);
        float2 b1 = __half22float2(*(const __half2*)&hv1.y);
        float2 b2 = __half22float2(*(const __half2*)&hv1.z);
        float2 b3 = __half22float2(*(const __half2*)&hv1.w);
        acc[0] += a0.x * ee0 + b0.x * ee1;
        acc[1] += a0.y * ee0 + b0.y * ee1;
        acc[2] += a1.x * ee0 + b1.x * ee1;
        acc[3] += a1.y * ee0 + b1.y * ee1;
        acc[4] += a2.x * ee0 + b2.x * ee1;
        acc[5] += a2.y * ee0 + b2.y * ee1;
        acc[6] += a3.x * ee0 + b3.x * ee1;
        acc[7] += a3.y * ee0 + b3.y * ee1;
    }
    if (j < end) {
        int s0 = g_csrc[j];
        float4 as0 = ((const float4*)g_asrc)[s0];
        uint4 hv0 = *(const uint4*)&g_hh[(long long)s0 * HC + lane * 8];
        float e0 = head_sel(as0, hsel) + adh;
        e0 = e0 > 0.f ? e0 : 0.2f * e0;
        float ee0 = __expf(e0);
        wsum += ee0;
        float2 a0 = __half22float2(*(const __half2*)&hv0.x);
        float2 a1 = __half22float2(*(const __half2*)&hv0.y);
        float2 a2 = __half22float2(*(const __half2*)&hv0.z);
        float2 a3 = __half22float2(*(const __half2*)&hv0.w);
        acc[0] += a0.x * ee0; acc[1] += a0.y * ee0;
        acc[2] += a1.x * ee0; acc[3] += a1.y * ee0;
        acc[4] += a2.x * ee0; acc[5] += a2.y * ee0;
        acc[6] += a3.x * ee0; acc[7] += a3.y * ee0;
    }

    float inv = 1.0f / wsum;
    int b = batch[w];
    float* pp = &g_pool[b * HC + lane * 8];
#pragma unroll
    for (int k = 0; k < 8; k++) {
        float v = acc[k] * inv + bias[lane * 8 + k];
        v = v > 0.f ? v : 0.01f * v;
        atomicAdd(&pp[k], v);
    }
    if (lane == 0) atomicAdd(&g_cnt[b], 1.0f);
}

// ---------------- 7: out = meanpool @ fc1_w + fc1_b (norm fused into load) ----------------
#define FBM 32
#define FBN 64
#define SPP 260
__global__ __launch_bounds__(256)
void fc_kernel(const float* __restrict__ fc1_w,
               const float* __restrict__ fc1_b,
               float* __restrict__ out) {
    __shared__ float sp[FBM * SPP];
    __shared__ float sw[32][FBN];
    __shared__ float sinv[FBM];
    const int g0  = blockIdx.y * FBM;
    const int n0  = blockIdx.x * FBN;
    const int tid = threadIdx.x;

    if (tid < FBM) sinv[tid] = 1.0f / fmaxf(g_cnt[g0 + tid], 1.0f);
    __syncthreads();

#pragma unroll
    for (int it = 0; it < 8; it++) {
        int i = tid + it * 256;
        int r = i >> 6;
        int c = (i & 63) * 4;
        float4 v = *(const float4*)&g_pool[(g0 + r) * HC + c];
        float inv = sinv[r];
        *(float4*)&sp[r * SPP + c] = make_float4(v.x * inv, v.y * inv, v.z * inv, v.w * inv);
    }

    const int row = tid >> 3;
    const int cg  = (tid & 7) * 8;
    float acc[8];
#pragma unroll
    for (int j = 0; j < 8; j++) acc[j] = 0.0f;

    for (int k0 = 0; k0 < HC; k0 += 32) {
        __syncthreads();
#pragma unroll
        for (int it = 0; it < 2; it++) {
            int i = tid + it * 256;
            int r = i >> 4;
            int c = (i & 15) * 4;
            *(float4*)&sw[r][c] = *(const float4*)&fc1_w[(k0 + r) * FOUT + n0 + c];
        }
        __syncthreads();
#pragma unroll
        for (int kk = 0; kk < 32; kk++) {
            float p = sp[row * SPP + k0 + kk];
            float4 w0 = *(const float4*)&sw[kk][cg];
            float4 w1 = *(const float4*)&sw[kk][cg + 4];
            acc[0] += p * w0.x; acc[1] += p * w0.y;
            acc[2] += p * w0.z; acc[3] += p * w0.w;
            acc[4] += p * w1.x; acc[5] += p * w1.y;
            acc[6] += p * w1.z; acc[7] += p * w1.w;
        }
    }
#pragma unroll
    for (int j = 0; j < 8; j++) acc[j] += fc1_b[n0 + cg + j];
    *(float4*)&out[(g0 + row) * FOUT + n0 + cg]     = make_float4(acc[0], acc[1], acc[2], acc[3]);
    *(float4*)&out[(g0 + row) * FOUT + n0 + cg + 4] = make_float4(acc[4], acc[5], acc[6], acc[7]);
}

// ---------------- launch ----------------
extern "C" void kernel_launch(void* const* d_in, const int* in_sizes, int n_in,
                              void* d_out, int out_size) {
    const float* x     = (const float*)d_in[0];
    const int*   ei    = (const int*)d_in[1];
    const int*   batch = (const int*)d_in[2];
    const float* lin_w = (const float*)d_in[3];
    const float* att_s = (const float*)d_in[4];
    const float* att_d = (const float*)d_in[5];
    const float* bias  = (const float*)d_in[6];
    const float* fc1_w = (const float*)d_in[7];
    const float* fc1_b = (const float*)d_in[8];
    float* out = (float*)d_out;

    int M = in_sizes[2];       // nodes
    int E = in_sizes[1] / 2;   // edges
    int total = E + M;

    int initN = M > GRAPHS * HC ? M : GRAPHS * HC;
    init_kernel<<<(initN + 255) / 256, 256>>>(M);                      // 0

    int convN = M * (KPAD / 4);
    if (convN < KPAD * (HC / 4)) convN = KPAD * (HC / 4);
    convert_kernel<<<(convN + 255) / 256, 256>>>(x, lin_w, M);         // 1

    edge_count_kernel<<<(E + 255) / 256, 256>>>(ei, E);                // 2

    cudaFuncSetAttribute(gemm_h_kernel,
                         cudaFuncAttributeMaxDynamicSharedMemorySize, SMTOT);
    dim3 ggrid(2, (M + BM - 1) / BM);
    gemm_h_kernel<<<ggrid, 256, SMTOT>>>(att_s, att_d, M);             // 3 <- ncu slot

    int nb = (M + 1023) / 1024;
    scan1_kernel<<<nb, 1024>>>(M);                                     // 4
    scan2_kernel<<<1, 64>>>(nb);                                       // 5
    scan3_kernel<<<(M + 255) / 256, 256>>>(M);                         // 6

    edge_fill_kernel<<<(total + 255) / 256, 256>>>(ei, E, M);          // 7

    aggregate_kernel<<<(M * 32 + 255) / 256, 256>>>(batch, bias, M);   // 8

    dim3 fgrid(FOUT / FBN, GRAPHS / FBM);
    fc_kernel<<<fgrid, 256>>>(fc1_w, fc1_b, out);                      // 9
}

// round 15
// speedup vs baseline: 1.3569x; 1.3569x over previous
#include <cuda_runtime.h>
#include <cuda_fp16.h>
#include <mma.h>
#include <cstdint>
using namespace nvcuda;

// Problem constants
#define NMAX   50000
#define EMAX   800000
#define TOTMAX (EMAX + NMAX)
#define GRAPHS 256
#define HC     256      // H*C
#define KIN    300      // n_in
#define KPAD   320      // padded K for fp16 GEMM
#define FOUT   768      // nout

// ---------------- scratch (device globals; no allocation) ----------------
__device__ __half g_xh[NMAX * KPAD];  // fp16 X, K padded with zeros
__device__ __half g_wh[KPAD * HC];    // fp16 W, K padded with zeros
__device__ __half g_hh[NMAX * HC];    // node features after linear, fp16 [N,256]
__device__ float  g_asrc[NMAX * 4];   // per-node src attention logits [N,4] (fp32)
__device__ float  g_adst[NMAX * 4];   // per-node dst attention logits [N,4] (fp32)
__device__ int    g_count[NMAX];      // in-degree EXCLUDING self-loop (memset 0)
__device__ int    g_scanex[NMAX];     // per-chunk exclusive scan
__device__ int    g_bsum[64];         // chunk totals -> chunk offsets
__device__ int    g_rowoff[NMAX];     // CSR row offsets
__device__ int    g_cursor[NMAX];     // fill cursors
__device__ int    g_csrc[TOTMAX];     // CSR-ordered src ids
__device__ float  g_pool[GRAPHS * HC];// per-graph sums [G,256] (memset 0)
__device__ float  g_cnt[GRAPHS];      // per-graph node counts (memset 0)

// ---------------- 1: convert X, W to fp16 (K padded to 320) ----------------
__global__ void convert_kernel(const float* __restrict__ X,
                               const float* __restrict__ W, int M) {
    int i = blockIdx.x * blockDim.x + threadIdx.x;
    if (i < M * (KPAD / 4)) {
        int row = i / (KPAD / 4);
        int c4  = (i % (KPAD / 4)) * 4;
        float4 v = make_float4(0.f, 0.f, 0.f, 0.f);
        if (c4 < KIN) v = *(const float4*)&X[row * KIN + c4];   // KIN divisible by 4
        *(__half2*)&g_xh[row * KPAD + c4]     = __float22half2_rn(make_float2(v.x, v.y));
        *(__half2*)&g_xh[row * KPAD + c4 + 2] = __float22half2_rn(make_float2(v.z, v.w));
    }
    if (i < KPAD * (HC / 4)) {
        int row = i / (HC / 4);
        int c4  = (i % (HC / 4)) * 4;
        float4 v = make_float4(0.f, 0.f, 0.f, 0.f);
        if (row < KIN) v = *(const float4*)&W[row * HC + c4];
        *(__half2*)&g_wh[row * HC + c4]     = __float22half2_rn(make_float2(v.x, v.y));
        *(__half2*)&g_wh[row * HC + c4 + 2] = __float22half2_rn(make_float2(v.z, v.w));
    }
}

// ---------------- 2: degree count (dst only; self-loop added later as +1) --------
__global__ void edge_count_kernel(const int* __restrict__ ei, int E) {
    int i = blockIdx.x * blockDim.x + threadIdx.x;
    if (i >= E) return;
    atomicAdd(&g_count[ei[E + i]], 1);
}

// ---------------- 3a: scan1 over (count+1) ----------------
__global__ void scan1_kernel(int M) {                     // block=1024
    __shared__ int sh[2][1024];
    int i = blockIdx.x * 1024 + threadIdx.x;
    int v = (i < M) ? (g_count[i] + 1) : 0;               // +1 = self-loop
    int buf = 0;
    sh[0][threadIdx.x] = v;
    __syncthreads();
#pragma unroll
    for (int off = 1; off < 1024; off <<= 1) {
        int nv = sh[buf][threadIdx.x];
        if (threadIdx.x >= off) nv += sh[buf][threadIdx.x - off];
        sh[1 - buf][threadIdx.x] = nv;
        buf = 1 - buf;
        __syncthreads();
    }
    int incl = sh[buf][threadIdx.x];
    if (i < M) g_scanex[i] = incl - v;
    if (threadIdx.x == 1023) g_bsum[blockIdx.x] = incl;
}

// ---------------- 4: GEMM h = xh @ wh via fp16 wmma (+ fused att dots) ----------
// Block 128x128, BKW=64 (4 k16 steps), 8 warps (4x2), warp tile 32x64. [R11-proven]
#define BM 128
#define BKW 64
#define KP 72     // A smem stride (half), 144B rows — ldmatrix conflict-free
#define NP 136    // B smem stride (half), 272B rows — ldmatrix conflict-free
#define SMRAW 35840
__global__ __launch_bounds__(256)
void gemm_h_kernel(const float* __restrict__ att_s,
                   const float* __restrict__ att_d,
                   int M) {
    __shared__ __align__(16) unsigned char smem_raw[SMRAW];
    __shared__ float s_as[128], s_ad[128];

    __half* Ah = (__half*)(smem_raw);
    __half* Bh = (__half*)(smem_raw + 18432);

    const int bx   = blockIdx.x;          // 0..1 -> N offset bx*128
    const int row0 = blockIdx.y * BM;
    const int tid  = threadIdx.x;
    const int warp = tid >> 5;
    const int lane = tid & 31;
    const int wm   = warp >> 1;           // 0..3 (M: wm*32)
    const int wn   = warp & 1;            // 0..1 (N: wn*64)

    if (tid < 128) { s_as[tid] = att_s[bx * 128 + tid]; s_ad[tid] = att_d[bx * 128 + tid]; }

    wmma::fragment<wmma::accumulator, 16, 16, 16, float> acc[2][4];
#pragma unroll
    for (int mt = 0; mt < 2; mt++)
#pragma unroll
        for (int nt = 0; nt < 4; nt++) wmma::fill_fragment(acc[mt][nt], 0.0f);

    for (int c = 0; c < KPAD / BKW; c++) {          // 5 chunks
        const int k0 = c * BKW;
#pragma unroll
        for (int it = 0; it < 4; it++) {
            int q   = tid + it * 256;
            int row = q >> 3;
            int c8  = (q & 7) * 8;
            int gr  = row0 + row;
            uint4 v = make_uint4(0u, 0u, 0u, 0u);
            if (gr < M) v = *(const uint4*)&g_xh[(long long)gr * KPAD + k0 + c8];
            *(uint4*)&Ah[row * KP + c8] = v;
        }
#pragma unroll
        for (int it = 0; it < 4; it++) {
            int q  = tid + it * 256;
            int kk = q >> 4;
            int c8 = (q & 15) * 8;
            uint4 v = *(const uint4*)&g_wh[(k0 + kk) * HC + bx * 128 + c8];
            *(uint4*)&Bh[kk * NP + c8] = v;
        }
        __syncthreads();
#pragma unroll
        for (int ks = 0; ks < 4; ks++) {
            int kk16 = ks * 16;
            wmma::fragment<wmma::matrix_a, 16, 16, 16, __half, wmma::row_major> af[2];
            wmma::fragment<wmma::matrix_b, 16, 16, 16, __half, wmma::row_major> bf[4];
#pragma unroll
            for (int mt = 0; mt < 2; mt++)
                wmma::load_matrix_sync(af[mt], &Ah[(wm * 32 + mt * 16) * KP + kk16], KP);
#pragma unroll
            for (int nt = 0; nt < 4; nt++)
                wmma::load_matrix_sync(bf[nt], &Bh[kk16 * NP + wn * 64 + nt * 16], NP);
#pragma unroll
            for (int mt = 0; mt < 2; mt++)
#pragma unroll
                for (int nt = 0; nt < 4; nt++)
                    wmma::mma_sync(acc[mt][nt], af[mt], bf[nt], acc[mt][nt]);
        }
        __syncthreads();
    }

    // epilogue: per-warp staging, fp16 h store + fused fp32 att dots
    float* eb = (float*)smem_raw + warp * 16 * 68;
#pragma unroll
    for (int mt = 0; mt < 2; mt++) {
#pragma unroll
        for (int nt = 0; nt < 4; nt++)
            wmma::store_matrix_sync(&eb[nt * 16], acc[mt][nt], 68, wmma::mem_row_major);
        __syncwarp();
        int r   = lane >> 1;
        int chh = (lane & 1) * 32;
        int gr  = row0 + wm * 32 + mt * 16 + r;
        float s = 0.f, d = 0.f;
#pragma unroll
        for (int j = 0; j < 8; j++) {
            float4 v = *(float4*)&eb[r * 68 + chh + j * 4];
            int cb = wn * 64 + chh + j * 4;
            s += v.x * s_as[cb] + v.y * s_as[cb + 1] + v.z * s_as[cb + 2] + v.w * s_as[cb + 3];
            d += v.x * s_ad[cb] + v.y * s_ad[cb + 1] + v.z * s_ad[cb + 2] + v.w * s_ad[cb + 3];
            if (gr < M) {
                *(__half2*)&g_hh[(long long)gr * HC + bx * 128 + cb]     =
                    __float22half2_rn(make_float2(v.x, v.y));
                *(__half2*)&g_hh[(long long)gr * HC + bx * 128 + cb + 2] =
                    __float22half2_rn(make_float2(v.z, v.w));
            }
        }
        s += __shfl_xor_sync(0xffffffffu, s, 1);
        d += __shfl_xor_sync(0xffffffffu, d, 1);
        if ((lane & 1) == 0 && gr < M) {
            g_asrc[gr * 4 + bx * 2 + wn] = s;
            g_adst[gr * 4 + bx * 2 + wn] = d;
        }
        __syncwarp();
    }
}

// ---------------- 3b: scan finish ----------------
__global__ void scan2_kernel(int nb) {                    // 1 block of 64 threads
    __shared__ int sh[2][64];
    int t = threadIdx.x;
    int v = (t < nb) ? g_bsum[t] : 0;
    int buf = 0;
    sh[0][t] = v;
    __syncthreads();
#pragma unroll
    for (int off = 1; off < 64; off <<= 1) {
        int nv = sh[buf][t];
        if (t >= off) nv += sh[buf][t - off];
        sh[1 - buf][t] = nv;
        buf = 1 - buf;
        __syncthreads();
    }
    if (t < nb) g_bsum[t] = sh[buf][t] - v;   // exclusive
}

__global__ void scan3_kernel(int M) {
    int i = blockIdx.x * blockDim.x + threadIdx.x;
    if (i >= M) return;
    int off = g_scanex[i] + g_bsum[i >> 10];
    g_rowoff[i] = off;
    g_cursor[i] = off;
}

// ---------------- 5: CSR fill (src ids only) ----------------
__global__ void edge_fill_kernel(const int* __restrict__ ei, int E, int M) {
    int i = blockIdx.x * blockDim.x + threadIdx.x;
    int total = E + M;
    if (i >= total) return;
    int s, d;
    if (i < E) { s = ei[i]; d = ei[E + i]; }
    else       { s = d = i - E; }
    int pos = atomicAdd(&g_cursor[d], 1);
    g_csrc[pos] = s;
}

// ---------------- 6: gather-aggregate, 8 nodes/warp, register pooling ----------------
__device__ __forceinline__ float head_sel(float4 v, int hsel) {
    return (hsel == 0) ? v.x : (hsel == 1) ? v.y : (hsel == 2) ? v.z : v.w;
}
#define CHN 8   // consecutive nodes per warp

__global__ void aggregate_kernel(const int* __restrict__ batch,
                                 const float* __restrict__ bias, int M) {
    int gw = blockIdx.x * (blockDim.x >> 5) + (threadIdx.x >> 5);
    int lane = threadIdx.x & 31;
    int n0 = gw * CHN;
    if (n0 >= M) return;
    int nend = n0 + CHN < M ? n0 + CHN : M;
    int hsel = lane >> 3;                      // head for this thread's 8 channels

    float bs[8];
#pragma unroll
    for (int k = 0; k < 8; k++) bs[k] = bias[lane * 8 + k];

    float pacc[8];
#pragma unroll
    for (int k = 0; k < 8; k++) pacc[k] = 0.0f;
    float cntloc = 0.0f;
    int curb = batch[n0];

    for (int w = n0; w < nend; w++) {
        int start = g_rowoff[w];
        int end   = start + g_count[w] + 1;     // +1 self-loop
        float adh = head_sel(((const float4*)g_adst)[w], hsel);

        float acc[8];
#pragma unroll
        for (int k = 0; k < 8; k++) acc[k] = 0.0f;
        float wsum = 0.0f;

        int j = start;
        for (; j + 2 <= end; j += 2) {
            int s0 = g_csrc[j];
            int s1 = g_csrc[j + 1];
            float4 as0 = ((const float4*)g_asrc)[s0];
            float4 as1 = ((const float4*)g_asrc)[s1];
            uint4 hv0 = *(const uint4*)&g_hh[(long long)s0 * HC + lane * 8];
            uint4 hv1 = *(const uint4*)&g_hh[(long long)s1 * HC + lane * 8];
            float e0 = head_sel(as0, hsel) + adh;
            float e1 = head_sel(as1, hsel) + adh;
            e0 = e0 > 0.f ? e0 : 0.2f * e0;
            e1 = e1 > 0.f ? e1 : 0.2f * e1;
            float ee0 = __expf(e0), ee1 = __expf(e1);
            wsum += ee0 + ee1;
            float2 a0 = __half22float2(*(const __half2*)&hv0.x);
            float2 a1 = __half22float2(*(const __half2*)&hv0.y);
            float2 a2 = __half22float2(*(const __half2*)&hv0.z);
            float2 a3 = __half22float2(*(const __half2*)&hv0.w);
            float2 b0 = __half22float2(*(const __half2*)&hv1.x);
            float2 b1 = __half22float2(*(const __half2*)&hv1.y);
            float2 b2 = __half22float2(*(const __half2*)&hv1.z);
            float2 b3 = __half22float2(*(const __half2*)&hv1.w);
            acc[0] += a0.x * ee0 + b0.x * ee1;
            acc[1] += a0.y * ee0 + b0.y * ee1;
            acc[2] += a1.x * ee0 + b1.x * ee1;
            acc[3] += a1.y * ee0 + b1.y * ee1;
            acc[4] += a2.x * ee0 + b2.x * ee1;
            acc[5] += a2.y * ee0 + b2.y * ee1;
            acc[6] += a3.x * ee0 + b3.x * ee1;
            acc[7] += a3.y * ee0 + b3.y * ee1;
        }
        if (j < end) {
            int s0 = g_csrc[j];
            float4 as0 = ((const float4*)g_asrc)[s0];
            uint4 hv0 = *(const uint4*)&g_hh[(long long)s0 * HC + lane * 8];
            float e0 = head_sel(as0, hsel) + adh;
            e0 = e0 > 0.f ? e0 : 0.2f * e0;
            float ee0 = __expf(e0);
            wsum += ee0;
            float2 a0 = __half22float2(*(const __half2*)&hv0.x);
            float2 a1 = __half22float2(*(const __half2*)&hv0.y);
            float2 a2 = __half22float2(*(const __half2*)&hv0.z);
            float2 a3 = __half22float2(*(const __half2*)&hv0.w);
            acc[0] += a0.x * ee0; acc[1] += a0.y * ee0;
            acc[2] += a1.x * ee0; acc[3] += a1.y * ee0;
            acc[4] += a2.x * ee0; acc[5] += a2.y * ee0;
            acc[6] += a3.x * ee0; acc[7] += a3.y * ee0;
        }

        int b = batch[w];
        if (b != curb) {   // flush register pool on graph change
            float* pp = &g_pool[curb * HC + lane * 8];
#pragma unroll
            for (int k = 0; k < 8; k++) { atomicAdd(&pp[k], pacc[k]); pacc[k] = 0.0f; }
            if (lane == 0) atomicAdd(&g_cnt[curb], cntloc);
            cntloc = 0.0f;
            curb = b;
        }
        float inv = 1.0f / wsum;
#pragma unroll
        for (int k = 0; k < 8; k++) {
            float v = acc[k] * inv + bs[k];
            v = v > 0.f ? v : 0.01f * v;
            pacc[k] += v;
        }
        cntloc += 1.0f;
    }
    // final flush
    {
        float* pp = &g_pool[curb * HC + lane * 8];
#pragma unroll
        for (int k = 0; k < 8; k++) atomicAdd(&pp[k], pacc[k]);
        if (lane == 0) atomicAdd(&g_cnt[curb], cntloc);
    }
}

// ---------------- 7: out = meanpool @ fc1_w + fc1_b (norm fused into load) ----------------
#define FBM 32
#define FBN 64
#define SPP 260
__global__ __launch_bounds__(256)
void fc_kernel(const float* __restrict__ fc1_w,
               const float* __restrict__ fc1_b,
               float* __restrict__ out) {
    __shared__ float sp[FBM * SPP];
    __shared__ float sw[32][FBN];
    __shared__ float sinv[FBM];
    const int g0  = blockIdx.y * FBM;
    const int n0  = blockIdx.x * FBN;
    const int tid = threadIdx.x;

    if (tid < FBM) sinv[tid] = 1.0f / fmaxf(g_cnt[g0 + tid], 1.0f);
    __syncthreads();

#pragma unroll
    for (int it = 0; it < 8; it++) {
        int i = tid + it * 256;
        int r = i >> 6;
        int c = (i & 63) * 4;
        float4 v = *(const float4*)&g_pool[(g0 + r) * HC + c];
        float inv = sinv[r];
        *(float4*)&sp[r * SPP + c] = make_float4(v.x * inv, v.y * inv, v.z * inv, v.w * inv);
    }

    const int row = tid >> 3;
    const int cg  = (tid & 7) * 8;
    float acc[8];
#pragma unroll
    for (int j = 0; j < 8; j++) acc[j] = 0.0f;

    for (int k0 = 0; k0 < HC; k0 += 32) {
        __syncthreads();
#pragma unroll
        for (int it = 0; it < 2; it++) {
            int i = tid + it * 256;
            int r = i >> 4;
            int c = (i & 15) * 4;
            *(float4*)&sw[r][c] = *(const float4*)&fc1_w[(k0 + r) * FOUT + n0 + c];
        }
        __syncthreads();
#pragma unroll
        for (int kk = 0; kk < 32; kk++) {
            float p = sp[row * SPP + k0 + kk];
            float4 w0 = *(const float4*)&sw[kk][cg];
            float4 w1 = *(const float4*)&sw[kk][cg + 4];
            acc[0] += p * w0.x; acc[1] += p * w0.y;
            acc[2] += p * w0.z; acc[3] += p * w0.w;
            acc[4] += p * w1.x; acc[5] += p * w1.y;
            acc[6] += p * w1.z; acc[7] += p * w1.w;
        }
    }
#pragma unroll
    for (int j = 0; j < 8; j++) acc[j] += fc1_b[n0 + cg + j];
    *(float4*)&out[(g0 + row) * FOUT + n0 + cg]     = make_float4(acc[0], acc[1], acc[2], acc[3]);
    *(float4*)&out[(g0 + row) * FOUT + n0 + cg + 4] = make_float4(acc[4], acc[5], acc[6], acc[7]);
}

// ---------------- launch ----------------
extern "C" void kernel_launch(void* const* d_in, const int* in_sizes, int n_in,
                              void* d_out, int out_size) {
    const float* x     = (const float*)d_in[0];
    const int*   ei    = (const int*)d_in[1];
    const int*   batch = (const int*)d_in[2];
    const float* att_s = (const float*)d_in[4];
    const float* att_d = (const float*)d_in[5];
    const float* lin_w = (const float*)d_in[3];
    const float* bias  = (const float*)d_in[6];
    const float* fc1_w = (const float*)d_in[7];
    const float* fc1_b = (const float*)d_in[8];
    float* out = (float*)d_out;

    int M = in_sizes[2];       // nodes
    int E = in_sizes[1] / 2;   // edges
    int total = E + M;

    // zero-init scratch via capturable memsets (no init kernel)
    void *pc = nullptr, *pp = nullptr, *pg = nullptr;
    cudaGetSymbolAddress(&pc, g_count);
    cudaGetSymbolAddress(&pp, g_pool);
    cudaGetSymbolAddress(&pg, g_cnt);
    cudaMemsetAsync(pc, 0, (size_t)M * sizeof(int));
    cudaMemsetAsync(pp, 0, (size_t)GRAPHS * HC * sizeof(float));
    cudaMemsetAsync(pg, 0, (size_t)GRAPHS * sizeof(float));

    int convN = M * (KPAD / 4);
    if (convN < KPAD * (HC / 4)) convN = KPAD * (HC / 4);
    convert_kernel<<<(convN + 255) / 256, 256>>>(x, lin_w, M);         // k0

    edge_count_kernel<<<(E + 255) / 256, 256>>>(ei, E);                // k1

    int nb = (M + 1023) / 1024;
    scan1_kernel<<<nb, 1024>>>(M);                                     // k2

    dim3 ggrid(2, (M + BM - 1) / BM);
    gemm_h_kernel<<<ggrid, 256>>>(att_s, att_d, M);                    // k3 <- ncu slot

    scan2_kernel<<<1, 64>>>(nb);                                       // k4
    scan3_kernel<<<(M + 255) / 256, 256>>>(M);                         // k5

    edge_fill_kernel<<<(total + 255) / 256, 256>>>(ei, E, M);          // k6

    int nwarps = (M + CHN - 1) / CHN;
    aggregate_kernel<<<(nwarps * 32 + 255) / 256, 256>>>(batch, bias, M);  // k7

    dim3 fgrid(FOUT / FBN, GRAPHS / FBM);
    fc_kernel<<<fgrid, 256>>>(fc1_w, fc1_b, out);                      // k8
}